// round 16
// baseline (speedup 1.0000x reference)
#include <cuda_runtime.h>
#include <cuda_bf16.h>
#include <math.h>
#include <stdint.h>

// ---------------- problem constants ----------------
#define SS   2048
#define BB   2
#define DD   768
#define HH   12
#define DHH  64
#define FF   3072
#define EE   8
#define TT   4096            // S*B
#define CAPN 1024            // capacity

// ---------------- device scratch ----------------
__device__ float g_qkv [(size_t)TT * 3 * DD];
__device__ float g_vT  [(size_t)BB * HH * DHH * SS];     // V transposed [b][h][dh][s]
__device__ float g_ctx [(size_t)TT * DD];
__device__ float g_attn[(size_t)TT * DD];
__device__ float g_x   [(size_t)TT * DD];
__device__ float g_y   [(size_t)EE * CAPN * DD];
__device__ float g_probs[(size_t)TT * EE];
__device__ __nv_bfloat16 g_bufb[(size_t)EE * CAPN * DD];
__device__ __nv_bfloat16 g_hb  [(size_t)EE * CAPN * FF];
__device__ __nv_bfloat16 g_w1b [(size_t)EE * DD * FF];   // [e][F][D] n-major
__device__ __nv_bfloat16 g_w2b [(size_t)EE * DD * FF];   // [e][D][F] n-major
__device__ int   g_eidx[TT];
__device__ int   g_pos [TT];
__device__ float g_gate[TT];
__device__ int   g_cnt    [EE];
__device__ int   g_cntfull[EE];

// ---------------- helpers ----------------
__device__ __forceinline__ float to_tf32(float x) {
    uint32_t u;
    asm("cvt.rna.tf32.f32 %0, %1;" : "=r"(u) : "f"(x));
    return __uint_as_float(u);
}
__device__ __forceinline__ uint32_t to_tf32_u(float x) {
    uint32_t u;
    asm("cvt.rna.tf32.f32 %0, %1;" : "=r"(u) : "f"(x));
    return u;
}

__device__ __forceinline__ void mma_tf32(
    float& c0, float& c1, float& c2, float& c3,
    uint32_t a0, uint32_t a1, uint32_t a2, uint32_t a3,
    uint32_t b0, uint32_t b1)
{
    asm volatile(
        "mma.sync.aligned.m16n8k8.row.col.f32.tf32.tf32.f32 "
        "{%0,%1,%2,%3}, {%4,%5,%6,%7}, {%8,%9}, {%0,%1,%2,%3};"
        : "+f"(c0), "+f"(c1), "+f"(c2), "+f"(c3)
        : "r"(a0), "r"(a1), "r"(a2), "r"(a3), "r"(b0), "r"(b1));
}

__device__ __forceinline__ void mma_bf16(
    float& c0, float& c1, float& c2, float& c3,
    uint32_t a0, uint32_t a1, uint32_t a2, uint32_t a3,
    uint32_t b0, uint32_t b1)
{
    asm volatile(
        "mma.sync.aligned.m16n8k16.row.col.f32.bf16.bf16.f32 "
        "{%0,%1,%2,%3}, {%4,%5,%6,%7}, {%8,%9}, {%0,%1,%2,%3};"
        : "+f"(c0), "+f"(c1), "+f"(c2), "+f"(c3)
        : "r"(a0), "r"(a1), "r"(a2), "r"(a3), "r"(b0), "r"(b1));
}

__device__ __forceinline__ void ldsm4(
    uint32_t& r0, uint32_t& r1, uint32_t& r2, uint32_t& r3, uint32_t addr)
{
    asm volatile(
        "ldmatrix.sync.aligned.m8n8.x4.shared.b16 {%0,%1,%2,%3}, [%4];"
        : "=r"(r0), "=r"(r1), "=r"(r2), "=r"(r3) : "r"(addr));
}

__device__ __forceinline__ void cp16(void* dst, const void* src) {
    uint32_t d = (uint32_t)__cvta_generic_to_shared(dst);
    asm volatile("cp.async.cg.shared.global [%0], [%1], 16;" :: "r"(d), "l"(src));
}
__device__ __forceinline__ void cp_commit() {
    asm volatile("cp.async.commit_group;");
}
template<int N>
__device__ __forceinline__ void cp_wait() {
    asm volatile("cp.async.wait_group %0;" :: "n"(N));
}

// ---------------- tiled transpose + fp32->bf16 convert ----------------
__global__ __launch_bounds__(256) void convert_t(
    const float* __restrict__ in, __nv_bfloat16* __restrict__ out, int R, int C)
{
    __shared__ float tile[32][33];
    int e = blockIdx.z;
    int c0 = blockIdx.x * 32, r0 = blockIdx.y * 32;
    const float* ip = in + (size_t)e * R * C;
    __nv_bfloat16* op = out + (size_t)e * R * C;
    int tx = threadIdx.x, ty = threadIdx.y;
    #pragma unroll
    for (int j = 0; j < 4; j++)
        tile[ty + j * 8][tx] = ip[(size_t)(r0 + ty + j * 8) * C + c0 + tx];
    __syncthreads();
    #pragma unroll
    for (int j = 0; j < 4; j++)
        op[(size_t)(c0 + ty + j * 8) * R + r0 + tx] = __float2bfloat16(tile[tx][ty + j * 8]);
}

// ======================================================================
// TF32 GEMM: C[M,N] = A[M,K] @ Bt[N,K]^T + bias. 3-stage cp.async.
// Inner loop EXACTLY the R6/R8 code. ROUNDOUT: tf32-round the epilogue.
// vT != nullptr: CTAs with n0 >= 2*DD write the V third transposed to
// vT[b][h][dh][s] instead of C (identical values; only layout differs).
// ======================================================================
#define ASTRIDE 36
#define ASZ     (128 * ASTRIDE)          // 4608 floats
#define TSTAGE  (2 * ASZ)                // A + B (both 128x36)

template<bool ROUNDOUT>
__global__ __launch_bounds__(256, 2) void gemm_tf32_bt(
    const float* __restrict__ A, const float* __restrict__ B,
    const float* __restrict__ bias, float* __restrict__ C,
    float* __restrict__ vT, int K, int N)
{
    extern __shared__ float smem[];

    const int tid  = threadIdx.x;
    const int lane = tid & 31;
    const int warp = tid >> 5;
    const int wm = (warp & 1) * 64;
    const int wn = (warp >> 1) * 32;
    const int n0 = blockIdx.x * 128;
    const int m0 = blockIdx.y * 128;

    const int sr = tid >> 1;
    const int sk = (tid & 1) * 16;

    auto issue = [&](int k0, float* As) {
        float* Bs = As + ASZ;
        const float* ap = A + (size_t)(m0 + sr) * K + k0 + sk;
        #pragma unroll
        for (int i = 0; i < 4; i++) cp16(&As[sr * ASTRIDE + sk + i * 4], ap + i * 4);
        const float* bp = B + (size_t)(n0 + sr) * K + k0 + sk;
        #pragma unroll
        for (int i = 0; i < 4; i++) cp16(&Bs[sr * ASTRIDE + sk + i * 4], bp + i * 4);
    };

    float acc[4][4][4];
    #pragma unroll
    for (int mi = 0; mi < 4; mi++)
        #pragma unroll
        for (int ni = 0; ni < 4; ni++)
            #pragma unroll
            for (int r = 0; r < 4; r++) acc[mi][ni][r] = 0.f;

    const int ntiles = K >> 5;
    issue(0, smem);           cp_commit();
    issue(32, smem + TSTAGE); cp_commit();

    const int afr = wm + (lane >> 2);
    const int afc = lane & 3;

    int sidx = 0;
    for (int t = 0; t < ntiles; t++) {
        float* As = smem + sidx * TSTAGE;
        float* Bs = As + ASZ;

        if (t + 1 < ntiles) cp_wait<1>(); else cp_wait<0>();
        __syncthreads();

        #pragma unroll
        for (int ks = 0; ks < 4; ks++) {
            uint32_t a[4][4], b[4][2];
            const int c = ks * 8 + afc;
            #pragma unroll
            for (int mi = 0; mi < 4; mi++) {
                const float* p = &As[(afr + mi * 16) * ASTRIDE + c];
                a[mi][0] = to_tf32_u(p[0]);
                a[mi][1] = to_tf32_u(p[8 * ASTRIDE]);
                a[mi][2] = to_tf32_u(p[4]);
                a[mi][3] = to_tf32_u(p[8 * ASTRIDE + 4]);
            }
            #pragma unroll
            for (int ni = 0; ni < 4; ni++) {
                const float* p = &Bs[(wn + ni * 8 + (lane >> 2)) * ASTRIDE + c];
                b[ni][0] = to_tf32_u(p[0]);
                b[ni][1] = to_tf32_u(p[4]);
            }
            #pragma unroll
            for (int mi = 0; mi < 4; mi++)
                #pragma unroll
                for (int ni = 0; ni < 4; ni++)
                    mma_tf32(acc[mi][ni][0], acc[mi][ni][1],
                             acc[mi][ni][2], acc[mi][ni][3],
                             a[mi][0], a[mi][1], a[mi][2], a[mi][3],
                             b[ni][0], b[ni][1]);
        }

        if (t + 2 < ntiles) {
            int widx = sidx + 2; if (widx >= 3) widx -= 3;
            issue((t + 2) << 5, smem + widx * TSTAGE);
            cp_commit();
        }
        if (++sidx == 3) sidx = 0;
    }

    const bool vpart = (vT != nullptr) && (n0 >= 2 * DD);

    #pragma unroll
    for (int mi = 0; mi < 4; mi++) {
        int r0 = m0 + wm + mi * 16 + (lane >> 2);
        #pragma unroll
        for (int ni = 0; ni < 4; ni++) {
            int c = n0 + wn + ni * 8 + 2 * (lane & 3);
            float bx = bias[c], by = bias[c + 1];
            float v0 = acc[mi][ni][0] + bx, v1 = acc[mi][ni][1] + by;
            float v2 = acc[mi][ni][2] + bx, v3 = acc[mi][ni][3] + by;
            if (ROUNDOUT) {
                v0 = to_tf32(v0); v1 = to_tf32(v1);
                v2 = to_tf32(v2); v3 = to_tf32(v3);
            }
            if (vpart) {
                int dhg = c - 2 * DD;
                int hh = dhg >> 6, dh = dhg & 63;
                int s0 = r0 >> 1, b0 = r0 & 1;
                float* base = vT + ((size_t)(b0 * HH + hh) * DHH) * SS;
                base[(size_t)dh * SS + s0]           = v0;
                base[(size_t)(dh + 1) * SS + s0]     = v1;
                base[(size_t)dh * SS + s0 + 4]       = v2;
                base[(size_t)(dh + 1) * SS + s0 + 4] = v3;
            } else {
                *(float2*)(C + (size_t)r0 * N + c)       = make_float2(v0, v1);
                *(float2*)(C + (size_t)(r0 + 8) * N + c) = make_float2(v2, v3);
            }
        }
    }
}

// ======================================================================
// BF16 MoE GEMM (exact R6/R8 version).
// ======================================================================
#define BFSTR   40
#define BFW     20
#define BFTILEW (128 * BFW)
#define BFSTAGE (2 * BFTILEW)

template<bool OUTBF>
__global__ __launch_bounds__(256, 2) void gemm_bf16_moe(
    const __nv_bfloat16* __restrict__ Aall, const __nv_bfloat16* __restrict__ Ball,
    const float* __restrict__ biasall, void* __restrict__ Call,
    int K, int N, int relu)
{
    extern __shared__ float smem[];
    uint32_t* W = (uint32_t*)smem;

    const int tid  = threadIdx.x;
    const int lane = tid & 31;
    const int warp = tid >> 5;
    const int wm = (warp & 1) * 64;
    const int wn = (warp >> 1) * 32;
    const int n0 = blockIdx.x * 128;
    const int m0 = blockIdx.y * 128;

    const int e = blockIdx.z;
    const int mlim = g_cnt[e];
    if (m0 >= mlim) return;
    const __nv_bfloat16* A = Aall + (size_t)e * CAPN * K;
    const __nv_bfloat16* B = Ball + (size_t)e * (size_t)N * K;
    const float* bias = biasall + (size_t)e * N;

    const int sr = tid >> 1;
    const int sk = (tid & 1) * 16;

    auto issue = [&](int k0, int stage) {
        __nv_bfloat16* As = (__nv_bfloat16*)(W + stage * BFSTAGE);
        __nv_bfloat16* Bs = (__nv_bfloat16*)(W + stage * BFSTAGE + BFTILEW);
        const __nv_bfloat16* ap = A + (size_t)(m0 + sr) * K + k0 + sk;
        cp16(&As[sr * BFSTR + sk], ap);
        cp16(&As[sr * BFSTR + sk + 8], ap + 8);
        const __nv_bfloat16* bp = B + (size_t)(n0 + sr) * K + k0 + sk;
        cp16(&Bs[sr * BFSTR + sk], bp);
        cp16(&Bs[sr * BFSTR + sk + 8], bp + 8);
    };

    float acc[4][4][4];
    #pragma unroll
    for (int mi = 0; mi < 4; mi++)
        #pragma unroll
        for (int ni = 0; ni < 4; ni++)
            #pragma unroll
            for (int r = 0; r < 4; r++) acc[mi][ni][r] = 0.f;

    const int ntiles = K >> 5;
    issue(0, 0);  cp_commit();
    issue(32, 1); cp_commit();
    issue(64, 2); cp_commit();

    for (int t = 0; t < ntiles; t++) {
        const uint32_t* Aw = W + (t & 3) * BFSTAGE;
        const uint32_t* Bw = Aw + BFTILEW;

        if (t + 2 < ntiles) cp_wait<2>();
        else if (t + 1 < ntiles) cp_wait<1>();
        else cp_wait<0>();
        __syncthreads();

        #pragma unroll
        for (int ks = 0; ks < 2; ks++) {
            uint32_t a[4][4], b[4][2];
            const int c = ks * 8 + (lane & 3);
            #pragma unroll
            for (int mi = 0; mi < 4; mi++) {
                const uint32_t* p = &Aw[(wm + mi * 16 + (lane >> 2)) * BFW + c];
                a[mi][0] = p[0];
                a[mi][1] = p[8 * BFW];
                a[mi][2] = p[4];
                a[mi][3] = p[8 * BFW + 4];
            }
            #pragma unroll
            for (int ni = 0; ni < 4; ni++) {
                const uint32_t* p = &Bw[(wn + ni * 8 + (lane >> 2)) * BFW + c];
                b[ni][0] = p[0];
                b[ni][1] = p[4];
            }
            #pragma unroll
            for (int mi = 0; mi < 4; mi++)
                #pragma unroll
                for (int ni = 0; ni < 4; ni++)
                    mma_bf16(acc[mi][ni][0], acc[mi][ni][1],
                             acc[mi][ni][2], acc[mi][ni][3],
                             a[mi][0], a[mi][1], a[mi][2], a[mi][3],
                             b[ni][0], b[ni][1]);
        }

        if (t + 3 < ntiles) {
            issue((t + 3) << 5, (t + 3) & 3);
            cp_commit();
        }
    }

    #pragma unroll
    for (int mi = 0; mi < 4; mi++) {
        int r0 = m0 + wm + mi * 16 + (lane >> 2);
        #pragma unroll
        for (int ni = 0; ni < 4; ni++) {
            int c = n0 + wn + ni * 8 + 2 * (lane & 3);
            float bx = bias[c], by = bias[c + 1];
            float v0 = acc[mi][ni][0] + bx, v1 = acc[mi][ni][1] + by;
            float v2 = acc[mi][ni][2] + bx, v3 = acc[mi][ni][3] + by;
            if (relu) {
                v0 = fmaxf(v0, 0.f); v1 = fmaxf(v1, 0.f);
                v2 = fmaxf(v2, 0.f); v3 = fmaxf(v3, 0.f);
            }
            if (OUTBF) {
                __nv_bfloat16* Ch = (__nv_bfloat16*)Call + (size_t)e * CAPN * N;
                if (r0 < mlim)
                    *(__nv_bfloat162*)(Ch + (size_t)r0 * N + c)       = __floats2bfloat162_rn(v0, v1);
                if (r0 + 8 < mlim)
                    *(__nv_bfloat162*)(Ch + (size_t)(r0 + 8) * N + c) = __floats2bfloat162_rn(v2, v3);
            } else {
                float* Cf = (float*)Call + (size_t)e * CAPN * N;
                if (r0 < mlim)     *(float2*)(Cf + (size_t)r0 * N + c)       = make_float2(v0, v1);
                if (r0 + 8 < mlim) *(float2*)(Cf + (size_t)(r0 + 8) * N + c) = make_float2(v2, v3);
            }
        }
    }
}

// ======================================================================
// TF32 flash attention: ABR=64, 128 threads, 4 CTAs/SM (wave-quantization
// fix). Per-warp computation identical to R14 (16 query rows each);
// ldmatrix fragments + shuffle P exchange. Values bitwise-identical.
// SMEM per stage: K[32][68] + VT[64][36] = 4480 floats; 2 stages.
// ======================================================================
#define ABR 64
#define ABC 32
#define AKV   2176          // K tile (32*68)
#define AVT   2304          // VT tile (64*36)
#define ASTG  (AKV + AVT)   // per stage
#define ASMEM (2 * ASTG * 4)

__global__ __launch_bounds__(128, 4) void attn_mma(
    const float* __restrict__ qkv, const float* __restrict__ vT,
    float* __restrict__ ctx)
{
    extern __shared__ float asm_[];

    const int bh = blockIdx.y;
    const int b = bh / HH, h = bh % HH;
    const int q0 = blockIdx.x * ABR;
    const int tid = threadIdx.x, lane = tid & 31, warp = tid >> 5;
    const int wm = warp * 16;

    // staging maps (128 threads)
    const int klr = tid >> 2;          // K: 0..31 kv row
    const int klc = (tid & 3) * 16;    // K: 0,16,32,48 dh col
    const int vdh = tid >> 1;          // VT: 0..63 dh row
    const int vkc = (tid & 1) * 16;    // VT: 0 or 16 kv col chunk

    const float* vtb = vT + ((size_t)(b * HH + h) * DHH) * SS;

    auto issue = [&](int kt, int st) {
        float* Kst = asm_ + st * ASTG;
        float* Vst = Kst + AKV;
        const float* kr = qkv + ((size_t)(kt + klr) * BB + b) * (3 * DD) + DD + h * DHH + klc;
        cp16(&Kst[klr * 68 + klc], kr);
        cp16(&Kst[klr * 68 + klc + 4], kr + 4);
        cp16(&Kst[klr * 68 + klc + 8], kr + 8);
        cp16(&Kst[klr * 68 + klc + 12], kr + 12);
        const float* vr = vtb + (size_t)vdh * SS + kt + vkc;
        cp16(&Vst[vdh * 36 + vkc], vr);
        cp16(&Vst[vdh * 36 + vkc + 4], vr + 4);
        cp16(&Vst[vdh * 36 + vkc + 8], vr + 8);
        cp16(&Vst[vdh * 36 + vkc + 12], vr + 12);
    };

    // Q fragments: qkv pre-rounded; *0.125f exact.
    uint32_t qa[8][4];
    {
        int ra = q0 + wm + (lane >> 2);
        int rb = ra + 8;
        const float* pa = qkv + ((size_t)ra * BB + b) * (3 * DD) + h * DHH;
        const float* pb = qkv + ((size_t)rb * BB + b) * (3 * DD) + h * DHH;
        #pragma unroll
        for (int kk = 0; kk < 8; kk++) {
            int c = kk * 8 + (lane & 3);
            qa[kk][0] = __float_as_uint(pa[c    ] * 0.125f);
            qa[kk][1] = __float_as_uint(pb[c    ] * 0.125f);
            qa[kk][2] = __float_as_uint(pa[c + 4] * 0.125f);
            qa[kk][3] = __float_as_uint(pb[c + 4] * 0.125f);
        }
    }

    float m0 = -1e30f, m1 = -1e30f, l0 = 0.f, l1 = 0.f;
    float o[8][4];
    #pragma unroll
    for (int ni = 0; ni < 8; ni++)
        #pragma unroll
        for (int r = 0; r < 4; r++) o[ni][r] = 0.f;

    const int pc  = 2 * (lane & 3);
    const int xsrc  = (lane & ~3) | ((lane & 3) >> 1);
    const int xsrc2 = xsrc + 2;
    const bool xodd = (lane & 1);

    const int lg = lane >> 3, lrr = lane & 7;

    issue(0, 0); cp_commit();

    const int NT = SS / ABC;
    for (int ti = 0; ti < NT; ti++) {
        cp_wait<0>();
        __syncthreads();
        if (ti + 1 < NT) { issue((ti + 1) * ABC, (ti + 1) & 1); cp_commit(); }

        const float* Kst = asm_ + (ti & 1) * ASTG;
        const float* Vst = Kst + AKV;

        const uint32_t ksh = (uint32_t)__cvta_generic_to_shared(Kst);
        const uint32_t vsh = (uint32_t)__cvta_generic_to_shared(Vst);
        const uint32_t kaddr = ksh + ((((lg >> 1) * 8 + lrr) * 68 + (lg & 1) * 4) << 2);
        const uint32_t vaddr = vsh + ((((lg >> 1) * 8 + lrr) * 36 + (lg & 1) * 4) << 2);

        float s[4][4];
        #pragma unroll
        for (int ni = 0; ni < 4; ni++)
            #pragma unroll
            for (int r = 0; r < 4; r++) s[ni][r] = 0.f;

        #pragma unroll
        for (int kk = 0; kk < 8; kk++) {
            uint32_t kb[4][2];
            ldsm4(kb[0][0], kb[0][1], kb[1][0], kb[1][1], kaddr + kk * 32);
            ldsm4(kb[2][0], kb[2][1], kb[3][0], kb[3][1], kaddr + kk * 32 + 16 * 68 * 4);
            #pragma unroll
            for (int ni = 0; ni < 4; ni++)
                mma_tf32(s[ni][0], s[ni][1], s[ni][2], s[ni][3],
                         qa[kk][0], qa[kk][1], qa[kk][2], qa[kk][3],
                         kb[ni][0], kb[ni][1]);
        }

        float mt0 = -1e30f, mt1 = -1e30f;
        #pragma unroll
        for (int ni = 0; ni < 4; ni++) {
            mt0 = fmaxf(mt0, fmaxf(s[ni][0], s[ni][1]));
            mt1 = fmaxf(mt1, fmaxf(s[ni][2], s[ni][3]));
        }
        mt0 = fmaxf(mt0, __shfl_xor_sync(0xffffffffu, mt0, 1));
        mt0 = fmaxf(mt0, __shfl_xor_sync(0xffffffffu, mt0, 2));
        mt1 = fmaxf(mt1, __shfl_xor_sync(0xffffffffu, mt1, 1));
        mt1 = fmaxf(mt1, __shfl_xor_sync(0xffffffffu, mt1, 2));
        float mn0 = fmaxf(m0, mt0), mn1 = fmaxf(m1, mt1);
        float f0 = __expf(m0 - mn0), f1 = __expf(m1 - mn1);
        m0 = mn0; m1 = mn1;
        l0 *= f0; l1 *= f1;
        #pragma unroll
        for (int ni = 0; ni < 8; ni++) {
            o[ni][0] *= f0; o[ni][1] *= f0;
            o[ni][2] *= f1; o[ni][3] *= f1;
        }

        float rs0 = 0.f, rs1 = 0.f;
        #pragma unroll
        for (int ni = 0; ni < 4; ni++) {
            float p00 = __expf(s[ni][0] - m0);
            float p01 = __expf(s[ni][1] - m0);
            float p10 = __expf(s[ni][2] - m1);
            float p11 = __expf(s[ni][3] - m1);
            rs0 += p00 + p01; rs1 += p10 + p11;

            float e00 = __shfl_sync(0xffffffffu, p00, xsrc);
            float o00 = __shfl_sync(0xffffffffu, p01, xsrc);
            float e10 = __shfl_sync(0xffffffffu, p10, xsrc);
            float o10 = __shfl_sync(0xffffffffu, p11, xsrc);
            float e04 = __shfl_sync(0xffffffffu, p00, xsrc2);
            float o04 = __shfl_sync(0xffffffffu, p01, xsrc2);
            float e14 = __shfl_sync(0xffffffffu, p10, xsrc2);
            float o14 = __shfl_sync(0xffffffffu, p11, xsrc2);
            uint32_t pfa[4];
            pfa[0] = to_tf32_u(xodd ? o00 : e00);
            pfa[1] = to_tf32_u(xodd ? o10 : e10);
            pfa[2] = to_tf32_u(xodd ? o04 : e04);
            pfa[3] = to_tf32_u(xodd ? o14 : e14);

            uint32_t vb[8][2];
            const uint32_t va = vaddr + ni * 32;
            ldsm4(vb[0][0], vb[0][1], vb[1][0], vb[1][1], va);
            ldsm4(vb[2][0], vb[2][1], vb[3][0], vb[3][1], va + 16 * 36 * 4);
            ldsm4(vb[4][0], vb[4][1], vb[5][0], vb[5][1], va + 32 * 36 * 4);
            ldsm4(vb[6][0], vb[6][1], vb[7][0], vb[7][1], va + 48 * 36 * 4);

            #pragma unroll
            for (int nj = 0; nj < 8; nj++)
                mma_tf32(o[nj][0], o[nj][1], o[nj][2], o[nj][3],
                         pfa[0], pfa[1], pfa[2], pfa[3], vb[nj][0], vb[nj][1]);
        }
        rs0 += __shfl_xor_sync(0xffffffffu, rs0, 1);
        rs0 += __shfl_xor_sync(0xffffffffu, rs0, 2);
        rs1 += __shfl_xor_sync(0xffffffffu, rs1, 1);
        rs1 += __shfl_xor_sync(0xffffffffu, rs1, 2);
        l0 += rs0; l1 += rs1;
    }

    float i0 = 1.f / l0, i1 = 1.f / l1;
    int ra = q0 + wm + (lane >> 2), rb = ra + 8;
    float* ca = ctx + ((size_t)ra * BB + b) * DD + h * DHH;
    float* cb = ctx + ((size_t)rb * BB + b) * DD + h * DHH;
    #pragma unroll
    for (int ni = 0; ni < 8; ni++) {
        int c = ni * 8 + pc;
        *(float2*)(ca + c) = make_float2(o[ni][0] * i0, o[ni][1] * i0);
        *(float2*)(cb + c) = make_float2(o[ni][2] * i1, o[ni][3] * i1);
    }
}

// ---------------- fused: x = LN(src+attn); router (bitwise-identical logits) --
__global__ __launch_bounds__(256) void add_ln_router(
    const float* __restrict__ a, const float* __restrict__ bvec,
    const float* __restrict__ g, const float* __restrict__ beta,
    const float* __restrict__ rw, const float* __restrict__ rb,
    float* __restrict__ xout)
{
    int t = blockIdx.x;
    __shared__ float row[DD];
    __shared__ float red[256];
    __shared__ float slog[EE];
    int tid = threadIdx.x;
    int warp = tid >> 5, lane = tid & 31;

    float s = 0.f;
    for (int d = tid; d < DD; d += 256) {
        float v = a[(size_t)t * DD + d] + bvec[(size_t)t * DD + d];
        row[d] = v; s += v;
    }
    red[tid] = s; __syncthreads();
    for (int o = 128; o > 0; o >>= 1) { if (tid < o) red[tid] += red[tid + o]; __syncthreads(); }
    float mean = red[0] * (1.f / DD);
    __syncthreads();
    float vs = 0.f;
    for (int d = tid; d < DD; d += 256) { float dv = row[d] - mean; vs += dv * dv; }
    red[tid] = vs; __syncthreads();
    for (int o = 128; o > 0; o >>= 1) { if (tid < o) red[tid] += red[tid + o]; __syncthreads(); }
    float rstd = rsqrtf(red[0] * (1.f / DD) + 1e-5f);
    __syncthreads();
    for (int d = tid; d < DD; d += 256) {
        float v = (row[d] - mean) * rstd * g[d] + beta[d];
        xout[(size_t)t * DD + d] = v;
        row[d] = v;
    }
    __syncthreads();

    float acc = 0.f;
    const float* we = rw + warp * DD;
    for (int d = lane; d < DD; d += 32) acc += row[d] * we[d];
    #pragma unroll
    for (int o = 16; o > 0; o >>= 1) acc += __shfl_xor_sync(0xffffffffu, acc, o);
    if (lane == 0) slog[warp] = acc + rb[warp];
    __syncthreads();

    if (tid == 0) {
        float pe[EE]; float mx = -1e30f;
        #pragma unroll
        for (int e = 0; e < EE; e++) { pe[e] = slog[e]; mx = fmaxf(mx, pe[e]); }
        float p[EE]; float sum = 0.f;
        #pragma unroll
        for (int e = 0; e < EE; e++) { p[e] = __expf(pe[e] - mx); sum += p[e]; }
        float inv = 1.f / sum;
        int best = 0; float bp = -1.f;
        #pragma unroll
        for (int e = 0; e < EE; e++) p[e] *= inv;
        #pragma unroll
        for (int e = 0; e < EE; e++) { if (p[e] > bp) { bp = p[e]; best = e; } }
        g_eidx[t] = best; g_gate[t] = bp;
        #pragma unroll
        for (int e = 0; e < EE; e++) g_probs[(size_t)t * EE + e] = p[e];
    }
}

// ---------------- per-expert queue positions ----------------
__global__ void pos_kernel() {
    int warp = threadIdx.x >> 5, lane = threadIdx.x & 31;
    if (warp >= EE) return;
    int base = 0;
    for (int t0 = 0; t0 < TT; t0 += 32) {
        int t = t0 + lane;
        bool m = (g_eidx[t] == warp);
        unsigned msk = __ballot_sync(0xffffffffu, m);
        if (m) g_pos[t] = base + __popc(msk & ((1u << lane) - 1u));
        base += __popc(msk);
    }
    if (lane == 0) {
        g_cntfull[warp] = base;
        g_cnt[warp] = base < CAPN ? base : CAPN;
    }
}

// ---------------- gather tokens into expert buffers (bf16) ----------------
__global__ __launch_bounds__(192) void gather_kernel(const float* __restrict__ x) {
    int t = blockIdx.x;
    int p = g_pos[t];
    if (p >= CAPN) return;
    int e = g_eidx[t];
    __nv_bfloat16* dst = g_bufb + ((size_t)e * CAPN + p) * DD + threadIdx.x * 4;
    const float4 v = ((const float4*)(x + (size_t)t * DD))[threadIdx.x];
    *(__nv_bfloat162*)(dst)     = __floats2bfloat162_rn(v.x, v.y);
    *(__nv_bfloat162*)(dst + 2) = __floats2bfloat162_rn(v.z, v.w);
}

// ---------------- final: out = LN(x + gate * y[eidx,pos]) ----------------
__global__ __launch_bounds__(256) void final_kernel(
    const float* __restrict__ x, const float* __restrict__ g,
    const float* __restrict__ beta, float* __restrict__ out)
{
    int t = blockIdx.x;
    __shared__ float row[DD];
    __shared__ float red[256];
    int tid = threadIdx.x;
    int p = g_pos[t], e = g_eidx[t];
    float ga = g_gate[t];
    bool keep = (p < CAPN);
    const float* yrow = g_y + ((size_t)e * CAPN + (keep ? p : 0)) * DD;

    float s = 0.f;
    for (int d = tid; d < DD; d += 256) {
        float v = x[(size_t)t * DD + d] + (keep ? ga * yrow[d] : 0.f);
        row[d] = v; s += v;
    }
    red[tid] = s; __syncthreads();
    for (int o = 128; o > 0; o >>= 1) { if (tid < o) red[tid] += red[tid + o]; __syncthreads(); }
    float mean = red[0] * (1.f / DD);
    __syncthreads();
    float vs = 0.f;
    for (int d = tid; d < DD; d += 256) { float dv = row[d] - mean; vs += dv * dv; }
    red[tid] = vs; __syncthreads();
    for (int o = 128; o > 0; o >>= 1) { if (tid < o) red[tid] += red[tid + o]; __syncthreads(); }
    float rstd = rsqrtf(red[0] * (1.f / DD) + 1e-5f);
    for (int d = tid; d < DD; d += 256)
        out[(size_t)t * DD + d] = (row[d] - mean) * rstd * g[d] + beta[d];
}

// ---------------- lb loss ----------------
__global__ void loss_kernel(float* __restrict__ out) {
    int warp = threadIdx.x >> 5, lane = threadIdx.x & 31;
    __shared__ float ps[EE];
    float s = 0.f;
    for (int t = lane; t < TT; t += 32) s += g_probs[(size_t)t * EE + warp];
    #pragma unroll
    for (int o = 16; o > 0; o >>= 1) s += __shfl_xor_sync(0xffffffffu, s, o);
    if (lane == 0) ps[warp] = s;
    __syncthreads();
    if (threadIdx.x == 0) {
        float acc = 0.f;
        for (int e = 0; e < EE; e++)
            acc += ((float)g_cntfull[e] / (float)TT) * (ps[e] / (float)TT);
        out[(size_t)TT * DD] = (float)EE * acc;
    }
}

// ---------------- launch ----------------
extern "C" void kernel_launch(void* const* d_in, const int* in_sizes, int n_in,
                              void* d_out, int out_size)
{
    const float* src   = (const float*)d_in[0];
    const float* inw   = (const float*)d_in[1];
    const float* inb   = (const float*)d_in[2];
    const float* outw  = (const float*)d_in[3];
    const float* outb  = (const float*)d_in[4];
    const float* n1g   = (const float*)d_in[5];
    const float* n1b   = (const float*)d_in[6];
    const float* rw    = (const float*)d_in[7];
    const float* rb    = (const float*)d_in[8];
    const float* w1    = (const float*)d_in[9];
    const float* b1    = (const float*)d_in[10];
    const float* w2    = (const float*)d_in[11];
    const float* b2    = (const float*)d_in[12];
    const float* n2g   = (const float*)d_in[13];
    const float* n2b   = (const float*)d_in[14];
    float* out = (float*)d_out;

    float *p_qkv, *p_vt, *p_ctx, *p_attn, *p_x, *p_y;
    __nv_bfloat16 *p_bufb, *p_hb, *p_w1b, *p_w2b;
    cudaGetSymbolAddress((void**)&p_qkv,  g_qkv);
    cudaGetSymbolAddress((void**)&p_vt,   g_vT);
    cudaGetSymbolAddress((void**)&p_ctx,  g_ctx);
    cudaGetSymbolAddress((void**)&p_attn, g_attn);
    cudaGetSymbolAddress((void**)&p_x,    g_x);
    cudaGetSymbolAddress((void**)&p_y,    g_y);
    cudaGetSymbolAddress((void**)&p_bufb, g_bufb);
    cudaGetSymbolAddress((void**)&p_hb,   g_hb);
    cudaGetSymbolAddress((void**)&p_w1b,  g_w1b);
    cudaGetSymbolAddress((void**)&p_w2b,  g_w2b);

    const int smem_tf = 3 * TSTAGE * 4;          // 110592 B
    const int smem_bf = 4 * BFSTAGE * 4;         // 81920 B
    cudaFuncSetAttribute(gemm_tf32_bt<true>,
                         cudaFuncAttributeMaxDynamicSharedMemorySize, smem_tf);
    cudaFuncSetAttribute(gemm_tf32_bt<false>,
                         cudaFuncAttributeMaxDynamicSharedMemorySize, smem_tf);
    cudaFuncSetAttribute(gemm_bf16_moe<true>,
                         cudaFuncAttributeMaxDynamicSharedMemorySize, smem_bf);
    cudaFuncSetAttribute(gemm_bf16_moe<false>,
                         cudaFuncAttributeMaxDynamicSharedMemorySize, smem_bf);
    cudaFuncSetAttribute(attn_mma,
                         cudaFuncAttributeMaxDynamicSharedMemorySize, ASMEM);

    // weight convert+transpose: w1[e][D][F]->[e][F][D], w2[e][F][D]->[e][D][F]
    convert_t<<<dim3(FF / 32, DD / 32, EE), dim3(32, 8)>>>(w1, p_w1b, DD, FF);
    convert_t<<<dim3(DD / 32, FF / 32, EE), dim3(32, 8)>>>(w2, p_w2b, FF, DD);

    // QKV = src @ in_proj_w^T + b (tf32-rounded; V third written transposed)
    gemm_tf32_bt<true><<<dim3((3 * DD) / 128, TT / 128), 256, smem_tf>>>(
        src, inw, inb, p_qkv, p_vt, DD, 3 * DD);

    // attention -> ctx (64-query CTAs, 4/SM; bitwise-identical values)
    attn_mma<<<dim3(SS / ABR, BB * HH), 128, ASMEM>>>(p_qkv, p_vt, p_ctx);

    // attn_out = ctx @ out_proj_w^T + b
    gemm_tf32_bt<false><<<dim3(DD / 128, TT / 128), 256, smem_tf>>>(
        p_ctx, outw, outb, p_attn, nullptr, DD, DD);

    // x = LN(src + attn_out) fused with router
    add_ln_router<<<TT, 256>>>(src, p_attn, n1g, n1b, rw, rb, p_x);

    pos_kernel<<<1, 256>>>();
    gather_kernel<<<TT, 192>>>(p_x);

    // expert FFN (bf16 tensor cores)
    gemm_bf16_moe<true><<<dim3(FF / 128, CAPN / 128, EE), 256, smem_bf>>>(
        p_bufb, p_w1b, b1, p_hb, DD, FF, 1);
    gemm_bf16_moe<false><<<dim3(DD / 128, CAPN / 128, EE), 256, smem_bf>>>(
        p_hb, p_w2b, b2, p_y, FF, DD, 0);

    // out = LN(x + gate*moe)
    final_kernel<<<TT, 256>>>(p_x, n2g, n2b, out);
    loss_kernel<<<1, 256>>>(out);
}

// round 17
// speedup vs baseline: 1.0985x; 1.0985x over previous
#include <cuda_runtime.h>
#include <cuda_bf16.h>
#include <math.h>
#include <stdint.h>

// ---------------- problem constants ----------------
#define SS   2048
#define BB   2
#define DD   768
#define HH   12
#define DHH  64
#define FF   3072
#define EE   8
#define TT   4096            // S*B
#define CAPN 1024            // capacity

// ---------------- device scratch ----------------
__device__ float g_qkv [(size_t)TT * 3 * DD];
__device__ float g_vT  [(size_t)BB * HH * DHH * SS];     // V transposed [b][h][dh][s]
__device__ float g_ctx [(size_t)TT * DD];
__device__ float g_attn[(size_t)TT * DD];
__device__ float g_x   [(size_t)TT * DD];
__device__ float g_y   [(size_t)EE * CAPN * DD];
__device__ float g_probs[(size_t)TT * EE];
__device__ __nv_bfloat16 g_bufb[(size_t)EE * CAPN * DD];
__device__ __nv_bfloat16 g_hb  [(size_t)EE * CAPN * FF];
__device__ __nv_bfloat16 g_w1b [(size_t)EE * DD * FF];   // [e][F][D] n-major
__device__ __nv_bfloat16 g_w2b [(size_t)EE * DD * FF];   // [e][D][F] n-major
__device__ int   g_eidx[TT];
__device__ int   g_pos [TT];
__device__ float g_gate[TT];
__device__ int   g_cnt    [EE];
__device__ int   g_cntfull[EE];

// ---------------- helpers ----------------
__device__ __forceinline__ float to_tf32(float x) {
    uint32_t u;
    asm("cvt.rna.tf32.f32 %0, %1;" : "=r"(u) : "f"(x));
    return __uint_as_float(u);
}
__device__ __forceinline__ uint32_t to_tf32_u(float x) {
    uint32_t u;
    asm("cvt.rna.tf32.f32 %0, %1;" : "=r"(u) : "f"(x));
    return u;
}

__device__ __forceinline__ void mma_tf32(
    float& c0, float& c1, float& c2, float& c3,
    uint32_t a0, uint32_t a1, uint32_t a2, uint32_t a3,
    uint32_t b0, uint32_t b1)
{
    asm volatile(
        "mma.sync.aligned.m16n8k8.row.col.f32.tf32.tf32.f32 "
        "{%0,%1,%2,%3}, {%4,%5,%6,%7}, {%8,%9}, {%0,%1,%2,%3};"
        : "+f"(c0), "+f"(c1), "+f"(c2), "+f"(c3)
        : "r"(a0), "r"(a1), "r"(a2), "r"(a3), "r"(b0), "r"(b1));
}

__device__ __forceinline__ void mma_bf16(
    float& c0, float& c1, float& c2, float& c3,
    uint32_t a0, uint32_t a1, uint32_t a2, uint32_t a3,
    uint32_t b0, uint32_t b1)
{
    asm volatile(
        "mma.sync.aligned.m16n8k16.row.col.f32.bf16.bf16.f32 "
        "{%0,%1,%2,%3}, {%4,%5,%6,%7}, {%8,%9}, {%0,%1,%2,%3};"
        : "+f"(c0), "+f"(c1), "+f"(c2), "+f"(c3)
        : "r"(a0), "r"(a1), "r"(a2), "r"(a3), "r"(b0), "r"(b1));
}

__device__ __forceinline__ void ldsm4(
    uint32_t& r0, uint32_t& r1, uint32_t& r2, uint32_t& r3, uint32_t addr)
{
    asm volatile(
        "ldmatrix.sync.aligned.m8n8.x4.shared.b16 {%0,%1,%2,%3}, [%4];"
        : "=r"(r0), "=r"(r1), "=r"(r2), "=r"(r3) : "r"(addr));
}

__device__ __forceinline__ void cp16(void* dst, const void* src) {
    uint32_t d = (uint32_t)__cvta_generic_to_shared(dst);
    asm volatile("cp.async.cg.shared.global [%0], [%1], 16;" :: "r"(d), "l"(src));
}
__device__ __forceinline__ void cp_commit() {
    asm volatile("cp.async.commit_group;");
}
template<int N>
__device__ __forceinline__ void cp_wait() {
    asm volatile("cp.async.wait_group %0;" :: "n"(N));
}

// ---------------- tiled transpose + fp32->bf16 convert (vectorized) --------
// Values identical per element to the scalar version; only transaction
// shapes change (LDG.128 reads, STG.64 packed bf16 writes).
__global__ __launch_bounds__(256) void convert_t(
    const float* __restrict__ in, __nv_bfloat16* __restrict__ out, int R, int C)
{
    __shared__ float tile[32][33];
    int e = blockIdx.z;
    int c0 = blockIdx.x * 32, r0 = blockIdx.y * 32;
    const float* ip = in + (size_t)e * R * C;
    __nv_bfloat16* op = out + (size_t)e * R * C;
    int t = threadIdx.x;

    {
        int rr = t >> 3, cb = (t & 7) * 4;
        float4 v = *(const float4*)(ip + (size_t)(r0 + rr) * C + c0 + cb);
        tile[rr][cb] = v.x; tile[rr][cb + 1] = v.y;
        tile[rr][cb + 2] = v.z; tile[rr][cb + 3] = v.w;
    }
    __syncthreads();
    {
        int cc = t >> 3, rb = (t & 7) * 4;
        __nv_bfloat162 p0 = __floats2bfloat162_rn(tile[rb    ][cc], tile[rb + 1][cc]);
        __nv_bfloat162 p1 = __floats2bfloat162_rn(tile[rb + 2][cc], tile[rb + 3][cc]);
        uint2 pk;
        pk.x = *(uint32_t*)&p0;
        pk.y = *(uint32_t*)&p1;
        *(uint2*)(op + (size_t)(c0 + cc) * R + r0 + rb) = pk;
    }
}

// ======================================================================
// TF32 GEMM: C[M,N] = A[M,K] @ Bt[N,K]^T + bias. 3-stage cp.async.
// Inner loop EXACTLY the R6/R8 code. ROUNDOUT: tf32-round the epilogue.
// vT != nullptr: CTAs with n0 >= 2*DD write the V third transposed to
// vT[b][h][dh][s] instead of C (identical values; only layout differs).
// ======================================================================
#define ASTRIDE 36
#define ASZ     (128 * ASTRIDE)          // 4608 floats
#define TSTAGE  (2 * ASZ)                // A + B (both 128x36)

template<bool ROUNDOUT>
__global__ __launch_bounds__(256, 2) void gemm_tf32_bt(
    const float* __restrict__ A, const float* __restrict__ B,
    const float* __restrict__ bias, float* __restrict__ C,
    float* __restrict__ vT, int K, int N)
{
    extern __shared__ float smem[];

    const int tid  = threadIdx.x;
    const int lane = tid & 31;
    const int warp = tid >> 5;
    const int wm = (warp & 1) * 64;
    const int wn = (warp >> 1) * 32;
    const int n0 = blockIdx.x * 128;
    const int m0 = blockIdx.y * 128;

    const int sr = tid >> 1;
    const int sk = (tid & 1) * 16;

    auto issue = [&](int k0, float* As) {
        float* Bs = As + ASZ;
        const float* ap = A + (size_t)(m0 + sr) * K + k0 + sk;
        #pragma unroll
        for (int i = 0; i < 4; i++) cp16(&As[sr * ASTRIDE + sk + i * 4], ap + i * 4);
        const float* bp = B + (size_t)(n0 + sr) * K + k0 + sk;
        #pragma unroll
        for (int i = 0; i < 4; i++) cp16(&Bs[sr * ASTRIDE + sk + i * 4], bp + i * 4);
    };

    float acc[4][4][4];
    #pragma unroll
    for (int mi = 0; mi < 4; mi++)
        #pragma unroll
        for (int ni = 0; ni < 4; ni++)
            #pragma unroll
            for (int r = 0; r < 4; r++) acc[mi][ni][r] = 0.f;

    const int ntiles = K >> 5;
    issue(0, smem);           cp_commit();
    issue(32, smem + TSTAGE); cp_commit();

    const int afr = wm + (lane >> 2);
    const int afc = lane & 3;

    int sidx = 0;
    for (int t = 0; t < ntiles; t++) {
        float* As = smem + sidx * TSTAGE;
        float* Bs = As + ASZ;

        if (t + 1 < ntiles) cp_wait<1>(); else cp_wait<0>();
        __syncthreads();

        #pragma unroll
        for (int ks = 0; ks < 4; ks++) {
            uint32_t a[4][4], b[4][2];
            const int c = ks * 8 + afc;
            #pragma unroll
            for (int mi = 0; mi < 4; mi++) {
                const float* p = &As[(afr + mi * 16) * ASTRIDE + c];
                a[mi][0] = to_tf32_u(p[0]);
                a[mi][1] = to_tf32_u(p[8 * ASTRIDE]);
                a[mi][2] = to_tf32_u(p[4]);
                a[mi][3] = to_tf32_u(p[8 * ASTRIDE + 4]);
            }
            #pragma unroll
            for (int ni = 0; ni < 4; ni++) {
                const float* p = &Bs[(wn + ni * 8 + (lane >> 2)) * ASTRIDE + c];
                b[ni][0] = to_tf32_u(p[0]);
                b[ni][1] = to_tf32_u(p[4]);
            }
            #pragma unroll
            for (int mi = 0; mi < 4; mi++)
                #pragma unroll
                for (int ni = 0; ni < 4; ni++)
                    mma_tf32(acc[mi][ni][0], acc[mi][ni][1],
                             acc[mi][ni][2], acc[mi][ni][3],
                             a[mi][0], a[mi][1], a[mi][2], a[mi][3],
                             b[ni][0], b[ni][1]);
        }

        if (t + 2 < ntiles) {
            int widx = sidx + 2; if (widx >= 3) widx -= 3;
            issue((t + 2) << 5, smem + widx * TSTAGE);
            cp_commit();
        }
        if (++sidx == 3) sidx = 0;
    }

    const bool vpart = (vT != nullptr) && (n0 >= 2 * DD);

    #pragma unroll
    for (int mi = 0; mi < 4; mi++) {
        int r0 = m0 + wm + mi * 16 + (lane >> 2);
        #pragma unroll
        for (int ni = 0; ni < 4; ni++) {
            int c = n0 + wn + ni * 8 + 2 * (lane & 3);
            float bx = bias[c], by = bias[c + 1];
            float v0 = acc[mi][ni][0] + bx, v1 = acc[mi][ni][1] + by;
            float v2 = acc[mi][ni][2] + bx, v3 = acc[mi][ni][3] + by;
            if (ROUNDOUT) {
                v0 = to_tf32(v0); v1 = to_tf32(v1);
                v2 = to_tf32(v2); v3 = to_tf32(v3);
            }
            if (vpart) {
                int dhg = c - 2 * DD;
                int hh = dhg >> 6, dh = dhg & 63;
                int s0 = r0 >> 1, b0 = r0 & 1;
                float* base = vT + ((size_t)(b0 * HH + hh) * DHH) * SS;
                base[(size_t)dh * SS + s0]           = v0;
                base[(size_t)(dh + 1) * SS + s0]     = v1;
                base[(size_t)dh * SS + s0 + 4]       = v2;
                base[(size_t)(dh + 1) * SS + s0 + 4] = v3;
            } else {
                *(float2*)(C + (size_t)r0 * N + c)       = make_float2(v0, v1);
                *(float2*)(C + (size_t)(r0 + 8) * N + c) = make_float2(v2, v3);
            }
        }
    }
}

// ======================================================================
// BF16 MoE GEMM (exact R6/R8 version).
// ======================================================================
#define BFSTR   40
#define BFW     20
#define BFTILEW (128 * BFW)
#define BFSTAGE (2 * BFTILEW)

template<bool OUTBF>
__global__ __launch_bounds__(256, 2) void gemm_bf16_moe(
    const __nv_bfloat16* __restrict__ Aall, const __nv_bfloat16* __restrict__ Ball,
    const float* __restrict__ biasall, void* __restrict__ Call,
    int K, int N, int relu)
{
    extern __shared__ float smem[];
    uint32_t* W = (uint32_t*)smem;

    const int tid  = threadIdx.x;
    const int lane = tid & 31;
    const int warp = tid >> 5;
    const int wm = (warp & 1) * 64;
    const int wn = (warp >> 1) * 32;
    const int n0 = blockIdx.x * 128;
    const int m0 = blockIdx.y * 128;

    const int e = blockIdx.z;
    const int mlim = g_cnt[e];
    if (m0 >= mlim) return;
    const __nv_bfloat16* A = Aall + (size_t)e * CAPN * K;
    const __nv_bfloat16* B = Ball + (size_t)e * (size_t)N * K;
    const float* bias = biasall + (size_t)e * N;

    const int sr = tid >> 1;
    const int sk = (tid & 1) * 16;

    auto issue = [&](int k0, int stage) {
        __nv_bfloat16* As = (__nv_bfloat16*)(W + stage * BFSTAGE);
        __nv_bfloat16* Bs = (__nv_bfloat16*)(W + stage * BFSTAGE + BFTILEW);
        const __nv_bfloat16* ap = A + (size_t)(m0 + sr) * K + k0 + sk;
        cp16(&As[sr * BFSTR + sk], ap);
        cp16(&As[sr * BFSTR + sk + 8], ap + 8);
        const __nv_bfloat16* bp = B + (size_t)(n0 + sr) * K + k0 + sk;
        cp16(&Bs[sr * BFSTR + sk], bp);
        cp16(&Bs[sr * BFSTR + sk + 8], bp + 8);
    };

    float acc[4][4][4];
    #pragma unroll
    for (int mi = 0; mi < 4; mi++)
        #pragma unroll
        for (int ni = 0; ni < 4; ni++)
            #pragma unroll
            for (int r = 0; r < 4; r++) acc[mi][ni][r] = 0.f;

    const int ntiles = K >> 5;
    issue(0, 0);  cp_commit();
    issue(32, 1); cp_commit();
    issue(64, 2); cp_commit();

    for (int t = 0; t < ntiles; t++) {
        const uint32_t* Aw = W + (t & 3) * BFSTAGE;
        const uint32_t* Bw = Aw + BFTILEW;

        if (t + 2 < ntiles) cp_wait<2>();
        else if (t + 1 < ntiles) cp_wait<1>();
        else cp_wait<0>();
        __syncthreads();

        #pragma unroll
        for (int ks = 0; ks < 2; ks++) {
            uint32_t a[4][4], b[4][2];
            const int c = ks * 8 + (lane & 3);
            #pragma unroll
            for (int mi = 0; mi < 4; mi++) {
                const uint32_t* p = &Aw[(wm + mi * 16 + (lane >> 2)) * BFW + c];
                a[mi][0] = p[0];
                a[mi][1] = p[8 * BFW];
                a[mi][2] = p[4];
                a[mi][3] = p[8 * BFW + 4];
            }
            #pragma unroll
            for (int ni = 0; ni < 4; ni++) {
                const uint32_t* p = &Bw[(wn + ni * 8 + (lane >> 2)) * BFW + c];
                b[ni][0] = p[0];
                b[ni][1] = p[4];
            }
            #pragma unroll
            for (int mi = 0; mi < 4; mi++)
                #pragma unroll
                for (int ni = 0; ni < 4; ni++)
                    mma_bf16(acc[mi][ni][0], acc[mi][ni][1],
                             acc[mi][ni][2], acc[mi][ni][3],
                             a[mi][0], a[mi][1], a[mi][2], a[mi][3],
                             b[ni][0], b[ni][1]);
        }

        if (t + 3 < ntiles) {
            issue((t + 3) << 5, (t + 3) & 3);
            cp_commit();
        }
    }

    #pragma unroll
    for (int mi = 0; mi < 4; mi++) {
        int r0 = m0 + wm + mi * 16 + (lane >> 2);
        #pragma unroll
        for (int ni = 0; ni < 4; ni++) {
            int c = n0 + wn + ni * 8 + 2 * (lane & 3);
            float bx = bias[c], by = bias[c + 1];
            float v0 = acc[mi][ni][0] + bx, v1 = acc[mi][ni][1] + by;
            float v2 = acc[mi][ni][2] + bx, v3 = acc[mi][ni][3] + by;
            if (relu) {
                v0 = fmaxf(v0, 0.f); v1 = fmaxf(v1, 0.f);
                v2 = fmaxf(v2, 0.f); v3 = fmaxf(v3, 0.f);
            }
            if (OUTBF) {
                __nv_bfloat16* Ch = (__nv_bfloat16*)Call + (size_t)e * CAPN * N;
                if (r0 < mlim)
                    *(__nv_bfloat162*)(Ch + (size_t)r0 * N + c)       = __floats2bfloat162_rn(v0, v1);
                if (r0 + 8 < mlim)
                    *(__nv_bfloat162*)(Ch + (size_t)(r0 + 8) * N + c) = __floats2bfloat162_rn(v2, v3);
            } else {
                float* Cf = (float*)Call + (size_t)e * CAPN * N;
                if (r0 < mlim)     *(float2*)(Cf + (size_t)r0 * N + c)       = make_float2(v0, v1);
                if (r0 + 8 < mlim) *(float2*)(Cf + (size_t)(r0 + 8) * N + c) = make_float2(v2, v3);
            }
        }
    }
}

// ======================================================================
// TF32 flash attention (exact R14 version): ABR=128, 256 threads,
// cp.async double-buffered K/VT + ldmatrix fragments + shuffle P exchange.
// SMEM per stage: K[32][68] + VT[64][36] = 4480 floats; 2 stages.
// ======================================================================
#define ABR 128
#define ABC 32
#define AKV   2176          // K tile (32*68)
#define AVT   2304          // VT tile (64*36)
#define ASTG  (AKV + AVT)   // per stage
#define ASMEM (2 * ASTG * 4)

__global__ __launch_bounds__(256, 2) void attn_mma(
    const float* __restrict__ qkv, const float* __restrict__ vT,
    float* __restrict__ ctx)
{
    extern __shared__ float asm_[];

    const int bh = blockIdx.y;
    const int b = bh / HH, h = bh % HH;
    const int q0 = blockIdx.x * ABR;
    const int tid = threadIdx.x, lane = tid & 31, warp = tid >> 5;
    const int wm = warp * 16;

    // staging maps
    const int klr = tid >> 3;          // K: 0..31 kv row
    const int klc = (tid & 7) * 8;     // K: 0..56 dh col
    const int vdh = tid >> 2;          // VT: 0..63 dh row
    const int vkc = (tid & 3) * 8;     // VT: 0..24 kv col chunk

    const float* vtb = vT + ((size_t)(b * HH + h) * DHH) * SS;

    auto issue = [&](int kt, int st) {
        float* Kst = asm_ + st * ASTG;
        float* Vst = Kst + AKV;
        const float* kr = qkv + ((size_t)(kt + klr) * BB + b) * (3 * DD) + DD + h * DHH + klc;
        cp16(&Kst[klr * 68 + klc], kr);
        cp16(&Kst[klr * 68 + klc + 4], kr + 4);
        const float* vr = vtb + (size_t)vdh * SS + kt + vkc;
        cp16(&Vst[vdh * 36 + vkc], vr);
        cp16(&Vst[vdh * 36 + vkc + 4], vr + 4);
    };

    // Q fragments: qkv pre-rounded; *0.125f exact.
    uint32_t qa[8][4];
    {
        int ra = q0 + wm + (lane >> 2);
        int rb = ra + 8;
        const float* pa = qkv + ((size_t)ra * BB + b) * (3 * DD) + h * DHH;
        const float* pb = qkv + ((size_t)rb * BB + b) * (3 * DD) + h * DHH;
        #pragma unroll
        for (int kk = 0; kk < 8; kk++) {
            int c = kk * 8 + (lane & 3);
            qa[kk][0] = __float_as_uint(pa[c    ] * 0.125f);
            qa[kk][1] = __float_as_uint(pb[c    ] * 0.125f);
            qa[kk][2] = __float_as_uint(pa[c + 4] * 0.125f);
            qa[kk][3] = __float_as_uint(pb[c + 4] * 0.125f);
        }
    }

    float m0 = -1e30f, m1 = -1e30f, l0 = 0.f, l1 = 0.f;
    float o[8][4];
    #pragma unroll
    for (int ni = 0; ni < 8; ni++)
        #pragma unroll
        for (int r = 0; r < 4; r++) o[ni][r] = 0.f;

    const int pc  = 2 * (lane & 3);
    const int xsrc  = (lane & ~3) | ((lane & 3) >> 1);
    const int xsrc2 = xsrc + 2;
    const bool xodd = (lane & 1);

    const int lg = lane >> 3, lrr = lane & 7;

    issue(0, 0); cp_commit();

    const int NT = SS / ABC;
    for (int ti = 0; ti < NT; ti++) {
        cp_wait<0>();
        __syncthreads();
        if (ti + 1 < NT) { issue((ti + 1) * ABC, (ti + 1) & 1); cp_commit(); }

        const float* Kst = asm_ + (ti & 1) * ASTG;
        const float* Vst = Kst + AKV;

        const uint32_t ksh = (uint32_t)__cvta_generic_to_shared(Kst);
        const uint32_t vsh = (uint32_t)__cvta_generic_to_shared(Vst);
        const uint32_t kaddr = ksh + ((((lg >> 1) * 8 + lrr) * 68 + (lg & 1) * 4) << 2);
        const uint32_t vaddr = vsh + ((((lg >> 1) * 8 + lrr) * 36 + (lg & 1) * 4) << 2);

        float s[4][4];
        #pragma unroll
        for (int ni = 0; ni < 4; ni++)
            #pragma unroll
            for (int r = 0; r < 4; r++) s[ni][r] = 0.f;

        #pragma unroll
        for (int kk = 0; kk < 8; kk++) {
            uint32_t kb[4][2];
            ldsm4(kb[0][0], kb[0][1], kb[1][0], kb[1][1], kaddr + kk * 32);
            ldsm4(kb[2][0], kb[2][1], kb[3][0], kb[3][1], kaddr + kk * 32 + 16 * 68 * 4);
            #pragma unroll
            for (int ni = 0; ni < 4; ni++)
                mma_tf32(s[ni][0], s[ni][1], s[ni][2], s[ni][3],
                         qa[kk][0], qa[kk][1], qa[kk][2], qa[kk][3],
                         kb[ni][0], kb[ni][1]);
        }

        float mt0 = -1e30f, mt1 = -1e30f;
        #pragma unroll
        for (int ni = 0; ni < 4; ni++) {
            mt0 = fmaxf(mt0, fmaxf(s[ni][0], s[ni][1]));
            mt1 = fmaxf(mt1, fmaxf(s[ni][2], s[ni][3]));
        }
        mt0 = fmaxf(mt0, __shfl_xor_sync(0xffffffffu, mt0, 1));
        mt0 = fmaxf(mt0, __shfl_xor_sync(0xffffffffu, mt0, 2));
        mt1 = fmaxf(mt1, __shfl_xor_sync(0xffffffffu, mt1, 1));
        mt1 = fmaxf(mt1, __shfl_xor_sync(0xffffffffu, mt1, 2));
        float mn0 = fmaxf(m0, mt0), mn1 = fmaxf(m1, mt1);
        float f0 = __expf(m0 - mn0), f1 = __expf(m1 - mn1);
        m0 = mn0; m1 = mn1;
        l0 *= f0; l1 *= f1;
        #pragma unroll
        for (int ni = 0; ni < 8; ni++) {
            o[ni][0] *= f0; o[ni][1] *= f0;
            o[ni][2] *= f1; o[ni][3] *= f1;
        }

        float rs0 = 0.f, rs1 = 0.f;
        #pragma unroll
        for (int ni = 0; ni < 4; ni++) {
            float p00 = __expf(s[ni][0] - m0);
            float p01 = __expf(s[ni][1] - m0);
            float p10 = __expf(s[ni][2] - m1);
            float p11 = __expf(s[ni][3] - m1);
            rs0 += p00 + p01; rs1 += p10 + p11;

            float e00 = __shfl_sync(0xffffffffu, p00, xsrc);
            float o00 = __shfl_sync(0xffffffffu, p01, xsrc);
            float e10 = __shfl_sync(0xffffffffu, p10, xsrc);
            float o10 = __shfl_sync(0xffffffffu, p11, xsrc);
            float e04 = __shfl_sync(0xffffffffu, p00, xsrc2);
            float o04 = __shfl_sync(0xffffffffu, p01, xsrc2);
            float e14 = __shfl_sync(0xffffffffu, p10, xsrc2);
            float o14 = __shfl_sync(0xffffffffu, p11, xsrc2);
            uint32_t pfa[4];
            pfa[0] = to_tf32_u(xodd ? o00 : e00);
            pfa[1] = to_tf32_u(xodd ? o10 : e10);
            pfa[2] = to_tf32_u(xodd ? o04 : e04);
            pfa[3] = to_tf32_u(xodd ? o14 : e14);

            uint32_t vb[8][2];
            const uint32_t va = vaddr + ni * 32;
            ldsm4(vb[0][0], vb[0][1], vb[1][0], vb[1][1], va);
            ldsm4(vb[2][0], vb[2][1], vb[3][0], vb[3][1], va + 16 * 36 * 4);
            ldsm4(vb[4][0], vb[4][1], vb[5][0], vb[5][1], va + 32 * 36 * 4);
            ldsm4(vb[6][0], vb[6][1], vb[7][0], vb[7][1], va + 48 * 36 * 4);

            #pragma unroll
            for (int nj = 0; nj < 8; nj++)
                mma_tf32(o[nj][0], o[nj][1], o[nj][2], o[nj][3],
                         pfa[0], pfa[1], pfa[2], pfa[3], vb[nj][0], vb[nj][1]);
        }
        rs0 += __shfl_xor_sync(0xffffffffu, rs0, 1);
        rs0 += __shfl_xor_sync(0xffffffffu, rs0, 2);
        rs1 += __shfl_xor_sync(0xffffffffu, rs1, 1);
        rs1 += __shfl_xor_sync(0xffffffffu, rs1, 2);
        l0 += rs0; l1 += rs1;
    }

    float i0 = 1.f / l0, i1 = 1.f / l1;
    int ra = q0 + wm + (lane >> 2), rb = ra + 8;
    float* ca = ctx + ((size_t)ra * BB + b) * DD + h * DHH;
    float* cb = ctx + ((size_t)rb * BB + b) * DD + h * DHH;
    #pragma unroll
    for (int ni = 0; ni < 8; ni++) {
        int c = ni * 8 + pc;
        *(float2*)(ca + c) = make_float2(o[ni][0] * i0, o[ni][1] * i0);
        *(float2*)(cb + c) = make_float2(o[ni][2] * i1, o[ni][3] * i1);
    }
}

// ---------------- fused: x = LN(src+attn); router (bitwise-identical logits) --
__global__ __launch_bounds__(256) void add_ln_router(
    const float* __restrict__ a, const float* __restrict__ bvec,
    const float* __restrict__ g, const float* __restrict__ beta,
    const float* __restrict__ rw, const float* __restrict__ rb,
    float* __restrict__ xout)
{
    int t = blockIdx.x;
    __shared__ float row[DD];
    __shared__ float red[256];
    __shared__ float slog[EE];
    int tid = threadIdx.x;
    int warp = tid >> 5, lane = tid & 31;

    float s = 0.f;
    for (int d = tid; d < DD; d += 256) {
        float v = a[(size_t)t * DD + d] + bvec[(size_t)t * DD + d];
        row[d] = v; s += v;
    }
    red[tid] = s; __syncthreads();
    for (int o = 128; o > 0; o >>= 1) { if (tid < o) red[tid] += red[tid + o]; __syncthreads(); }
    float mean = red[0] * (1.f / DD);
    __syncthreads();
    float vs = 0.f;
    for (int d = tid; d < DD; d += 256) { float dv = row[d] - mean; vs += dv * dv; }
    red[tid] = vs; __syncthreads();
    for (int o = 128; o > 0; o >>= 1) { if (tid < o) red[tid] += red[tid + o]; __syncthreads(); }
    float rstd = rsqrtf(red[0] * (1.f / DD) + 1e-5f);
    __syncthreads();
    for (int d = tid; d < DD; d += 256) {
        float v = (row[d] - mean) * rstd * g[d] + beta[d];
        xout[(size_t)t * DD + d] = v;
        row[d] = v;
    }
    __syncthreads();

    float acc = 0.f;
    const float* we = rw + warp * DD;
    for (int d = lane; d < DD; d += 32) acc += row[d] * we[d];
    #pragma unroll
    for (int o = 16; o > 0; o >>= 1) acc += __shfl_xor_sync(0xffffffffu, acc, o);
    if (lane == 0) slog[warp] = acc + rb[warp];
    __syncthreads();

    if (tid == 0) {
        float pe[EE]; float mx = -1e30f;
        #pragma unroll
        for (int e = 0; e < EE; e++) { pe[e] = slog[e]; mx = fmaxf(mx, pe[e]); }
        float p[EE]; float sum = 0.f;
        #pragma unroll
        for (int e = 0; e < EE; e++) { p[e] = __expf(pe[e] - mx); sum += p[e]; }
        float inv = 1.f / sum;
        int best = 0; float bp = -1.f;
        #pragma unroll
        for (int e = 0; e < EE; e++) p[e] *= inv;
        #pragma unroll
        for (int e = 0; e < EE; e++) { if (p[e] > bp) { bp = p[e]; best = e; } }
        g_eidx[t] = best; g_gate[t] = bp;
        #pragma unroll
        for (int e = 0; e < EE; e++) g_probs[(size_t)t * EE + e] = p[e];
    }
}

// ---------------- per-expert queue positions ----------------
__global__ void pos_kernel() {
    int warp = threadIdx.x >> 5, lane = threadIdx.x & 31;
    if (warp >= EE) return;
    int base = 0;
    for (int t0 = 0; t0 < TT; t0 += 32) {
        int t = t0 + lane;
        bool m = (g_eidx[t] == warp);
        unsigned msk = __ballot_sync(0xffffffffu, m);
        if (m) g_pos[t] = base + __popc(msk & ((1u << lane) - 1u));
        base += __popc(msk);
    }
    if (lane == 0) {
        g_cntfull[warp] = base;
        g_cnt[warp] = base < CAPN ? base : CAPN;
    }
}

// ---------------- gather tokens into expert buffers (bf16) ----------------
__global__ __launch_bounds__(192) void gather_kernel(const float* __restrict__ x) {
    int t = blockIdx.x;
    int p = g_pos[t];
    if (p >= CAPN) return;
    int e = g_eidx[t];
    __nv_bfloat16* dst = g_bufb + ((size_t)e * CAPN + p) * DD + threadIdx.x * 4;
    const float4 v = ((const float4*)(x + (size_t)t * DD))[threadIdx.x];
    *(__nv_bfloat162*)(dst)     = __floats2bfloat162_rn(v.x, v.y);
    *(__nv_bfloat162*)(dst + 2) = __floats2bfloat162_rn(v.z, v.w);
}

// ---------------- final: out = LN(x + gate * y[eidx,pos]) ----------------
__global__ __launch_bounds__(256) void final_kernel(
    const float* __restrict__ x, const float* __restrict__ g,
    const float* __restrict__ beta, float* __restrict__ out)
{
    int t = blockIdx.x;
    __shared__ float row[DD];
    __shared__ float red[256];
    int tid = threadIdx.x;
    int p = g_pos[t], e = g_eidx[t];
    float ga = g_gate[t];
    bool keep = (p < CAPN);
    const float* yrow = g_y + ((size_t)e * CAPN + (keep ? p : 0)) * DD;

    float s = 0.f;
    for (int d = tid; d < DD; d += 256) {
        float v = x[(size_t)t * DD + d] + (keep ? ga * yrow[d] : 0.f);
        row[d] = v; s += v;
    }
    red[tid] = s; __syncthreads();
    for (int o = 128; o > 0; o >>= 1) { if (tid < o) red[tid] += red[tid + o]; __syncthreads(); }
    float mean = red[0] * (1.f / DD);
    __syncthreads();
    float vs = 0.f;
    for (int d = tid; d < DD; d += 256) { float dv = row[d] - mean; vs += dv * dv; }
    red[tid] = vs; __syncthreads();
    for (int o = 128; o > 0; o >>= 1) { if (tid < o) red[tid] += red[tid + o]; __syncthreads(); }
    float rstd = rsqrtf(red[0] * (1.f / DD) + 1e-5f);
    for (int d = tid; d < DD; d += 256)
        out[(size_t)t * DD + d] = (row[d] - mean) * rstd * g[d] + beta[d];
}

// ---------------- lb loss ----------------
__global__ void loss_kernel(float* __restrict__ out) {
    int warp = threadIdx.x >> 5, lane = threadIdx.x & 31;
    __shared__ float ps[EE];
    float s = 0.f;
    for (int t = lane; t < TT; t += 32) s += g_probs[(size_t)t * EE + warp];
    #pragma unroll
    for (int o = 16; o > 0; o >>= 1) s += __shfl_xor_sync(0xffffffffu, s, o);
    if (lane == 0) ps[warp] = s;
    __syncthreads();
    if (threadIdx.x == 0) {
        float acc = 0.f;
        for (int e = 0; e < EE; e++)
            acc += ((float)g_cntfull[e] / (float)TT) * (ps[e] / (float)TT);
        out[(size_t)TT * DD] = (float)EE * acc;
    }
}

// ---------------- launch ----------------
extern "C" void kernel_launch(void* const* d_in, const int* in_sizes, int n_in,
                              void* d_out, int out_size)
{
    const float* src   = (const float*)d_in[0];
    const float* inw   = (const float*)d_in[1];
    const float* inb   = (const float*)d_in[2];
    const float* outw  = (const float*)d_in[3];
    const float* outb  = (const float*)d_in[4];
    const float* n1g   = (const float*)d_in[5];
    const float* n1b   = (const float*)d_in[6];
    const float* rw    = (const float*)d_in[7];
    const float* rb    = (const float*)d_in[8];
    const float* w1    = (const float*)d_in[9];
    const float* b1    = (const float*)d_in[10];
    const float* w2    = (const float*)d_in[11];
    const float* b2    = (const float*)d_in[12];
    const float* n2g   = (const float*)d_in[13];
    const float* n2b   = (const float*)d_in[14];
    float* out = (float*)d_out;

    float *p_qkv, *p_vt, *p_ctx, *p_attn, *p_x, *p_y;
    __nv_bfloat16 *p_bufb, *p_hb, *p_w1b, *p_w2b;
    cudaGetSymbolAddress((void**)&p_qkv,  g_qkv);
    cudaGetSymbolAddress((void**)&p_vt,   g_vT);
    cudaGetSymbolAddress((void**)&p_ctx,  g_ctx);
    cudaGetSymbolAddress((void**)&p_attn, g_attn);
    cudaGetSymbolAddress((void**)&p_x,    g_x);
    cudaGetSymbolAddress((void**)&p_y,    g_y);
    cudaGetSymbolAddress((void**)&p_bufb, g_bufb);
    cudaGetSymbolAddress((void**)&p_hb,   g_hb);
    cudaGetSymbolAddress((void**)&p_w1b,  g_w1b);
    cudaGetSymbolAddress((void**)&p_w2b,  g_w2b);

    const int smem_tf = 3 * TSTAGE * 4;          // 110592 B
    const int smem_bf = 4 * BFSTAGE * 4;         // 81920 B
    cudaFuncSetAttribute(gemm_tf32_bt<true>,
                         cudaFuncAttributeMaxDynamicSharedMemorySize, smem_tf);
    cudaFuncSetAttribute(gemm_tf32_bt<false>,
                         cudaFuncAttributeMaxDynamicSharedMemorySize, smem_tf);
    cudaFuncSetAttribute(gemm_bf16_moe<true>,
                         cudaFuncAttributeMaxDynamicSharedMemorySize, smem_bf);
    cudaFuncSetAttribute(gemm_bf16_moe<false>,
                         cudaFuncAttributeMaxDynamicSharedMemorySize, smem_bf);
    cudaFuncSetAttribute(attn_mma,
                         cudaFuncAttributeMaxDynamicSharedMemorySize, ASMEM);

    // weight convert+transpose: w1[e][D][F]->[e][F][D], w2[e][F][D]->[e][D][F]
    convert_t<<<dim3(FF / 32, DD / 32, EE), 256>>>(w1, p_w1b, DD, FF);
    convert_t<<<dim3(DD / 32, FF / 32, EE), 256>>>(w2, p_w2b, FF, DD);

    // QKV = src @ in_proj_w^T + b (tf32-rounded; V third written transposed)
    gemm_tf32_bt<true><<<dim3((3 * DD) / 128, TT / 128), 256, smem_tf>>>(
        src, inw, inb, p_qkv, p_vt, DD, 3 * DD);

    // attention -> ctx (R14 exact: 128-query CTAs, ldmatrix fragments)
    attn_mma<<<dim3(SS / ABR, BB * HH), 256, ASMEM>>>(p_qkv, p_vt, p_ctx);

    // attn_out = ctx @ out_proj_w^T + b
    gemm_tf32_bt<false><<<dim3(DD / 128, TT / 128), 256, smem_tf>>>(
        p_ctx, outw, outb, p_attn, nullptr, DD, DD);

    // x = LN(src + attn_out) fused with router
    add_ln_router<<<TT, 256>>>(src, p_attn, n1g, n1b, rw, rb, p_x);

    pos_kernel<<<1, 256>>>();
    gather_kernel<<<TT, 192>>>(p_x);

    // expert FFN (bf16 tensor cores)
    gemm_bf16_moe<true><<<dim3(FF / 128, CAPN / 128, EE), 256, smem_bf>>>(
        p_bufb, p_w1b, b1, p_hb, DD, FF, 1);
    gemm_bf16_moe<false><<<dim3(DD / 128, CAPN / 128, EE), 256, smem_bf>>>(
        p_hb, p_w2b, b2, p_y, FF, DD, 0);

    // out = LN(x + gate*moe)
    final_kernel<<<TT, 256>>>(p_x, n2g, n2b, out);
    loss_kernel<<<1, 256>>>(out);
}